// round 11
// baseline (speedup 1.0000x reference)
#include <cuda_runtime.h>
#include <cuda_fp16.h>
#include <cstdint>

#define B_    16
#define CIN_  512
#define COUT_ 512
#define LAT_  512

#define XROWS  18496            // 16 * 34 * 34
#define XGUARD 64               // front zero rows
#define XTAIL  320              // tail zero rows (covers 256-row B tiles past end)
#define NT2    73               // ceil(18496/256)

// ---------------- device globals (allocation-free scratch) ------------------
__device__ float g_s[B_ * CIN_];
__device__ float g_wsq[COUT_ * CIN_];
__device__ float g_d[B_ * COUT_];
__device__ __half g_y[(size_t)B_ * COUT_ * 4 * 1156];    // [b][co][p][34][34] fp16

__device__ __align__(256) __half g_Ah[9ull * 512 * 512];   // [tap][co][ci]
__device__ __align__(256) __half g_Xh[(size_t)(XGUARD + XROWS + XTAIL) * 512];

// tap order grouped by parity: p0={0,2,6,8} p1={1,7} p2={3,5} p3={4}
__constant__ int c_tap[9]   = {0, 2, 6, 8, 1, 7, 3, 5, 4};
// shift[t] = (kh>>1)*34 + (kw>>1), indexed by tap id
__constant__ int c_shift[9] = {0, 0, 1, 0, 0, 1, 34, 34, 35};

// ---------------- helpers ---------------------------------------------------
__device__ __forceinline__ uint32_t smem_to_u32(const void* p) {
    uint32_t a;
    asm("{ .reg .u64 t; cvta.to.shared.u64 t, %1; cvt.u32.u64 %0, t; }"
        : "=r"(a) : "l"(p));
    return a;
}
__device__ __forceinline__ void cp16(uint32_t dst, const void* src) {
    asm volatile("cp.async.cg.shared.global [%0], [%1], 16;\n"
                 :: "r"(dst), "l"(src));
}
__device__ __forceinline__ void cp_commit() {
    asm volatile("cp.async.commit_group;\n" ::: "memory");
}
__device__ __forceinline__ void cp_wait1() {
    asm volatile("cp.async.wait_group 1;\n" ::: "memory");
}
__device__ __forceinline__ void ldsm_x4(uint32_t* r, uint32_t addr) {
    asm volatile("ldmatrix.sync.aligned.m8n8.x4.shared.b16 {%0,%1,%2,%3}, [%4];"
                 : "=r"(r[0]), "=r"(r[1]), "=r"(r[2]), "=r"(r[3]) : "r"(addr));
}
__device__ __forceinline__ void mma_fp16(float* d, const uint32_t* a,
                                         const uint32_t* b) {
    asm volatile(
        "mma.sync.aligned.m16n8k16.row.col.f32.f16.f16.f32 "
        "{%0,%1,%2,%3}, {%4,%5,%6,%7}, {%8,%9}, {%0,%1,%2,%3};"
        : "+f"(d[0]), "+f"(d[1]), "+f"(d[2]), "+f"(d[3])
        : "r"(a[0]), "r"(a[1]), "r"(a[2]), "r"(a[3]), "r"(b[0]), "r"(b[1]));
}
// smem tile rows of 64 fp16 (128B), xor-swizzled 16B chunks, 8-row period
__device__ __forceinline__ int swz(int row, int c8) {
    return row * 128 + ((c8 ^ (row & 7)) << 4);
}

// ---------------------------------------------------------------------------
__global__ void k_style(const float* __restrict__ w, const float* __restrict__ aw,
                        const float* __restrict__ ab) {
    int b = blockIdx.x, ci = threadIdx.x;
    const float* wr = w + b * LAT_;
    const float* ar = aw + (size_t)ci * LAT_;
    float acc = 0.f;
#pragma unroll 8
    for (int l = 0; l < LAT_; ++l) acc += wr[l] * ar[l];
    g_s[b * CIN_ + ci] = acc + ab[ci] + 1.0f;
}

__global__ void k_demod() {
    int b = blockIdx.x, co = threadIdx.x;
    __shared__ float s2[CIN_];
    for (int i = threadIdx.x; i < CIN_; i += blockDim.x) {
        float v = g_s[b * CIN_ + i];
        s2[i] = v * v;
    }
    __syncthreads();
    const float* wq = g_wsq + (size_t)co * CIN_;
    float a = 0.f;
#pragma unroll 8
    for (int ci = 0; ci < CIN_; ++ci) a += s2[ci] * wq[ci];
    g_d[b * COUT_ + co] = rsqrtf(a + 1e-8f);
}

// A prep + wsq (merged): g_Ah[tap][co][ci] = fp16(weight[co][ci][tap]),
// g_wsq[co][ci] = sum_t weight^2
__global__ __launch_bounds__(256) void k_prepw(const float* __restrict__ weight) {
    const int co = blockIdx.x;
#pragma unroll
    for (int r = 0; r < 2; ++r) {
        const int ci = threadIdx.x * 2 + r;
        const float* p = weight + ((size_t)co * 512 + ci) * 9;
        float sq = 0.f;
#pragma unroll
        for (int t = 0; t < 9; ++t) {
            float v = p[t];
            g_Ah[((size_t)t * 512 + co) * 512 + ci] = __float2half_rn(v);
            sq += v * v;
        }
        g_wsq[(size_t)co * 512 + ci] = sq;
    }
}

// Xp prep (+ guard zeroing merged in blockIdx.x==34 blocks):
// row n = b*1156 + r*34 + c ; Xp = x*s interior, 0 on r,c in {0,33}
__global__ __launch_bounds__(256) void k_prepx(const float* __restrict__ x) {
    __shared__ float xt[256][33];
    const int r = blockIdx.x;          // 0..33 normal, 34 = guard block
    const int b = blockIdx.y;
    const int tid = threadIdx.x;

    if (r == 34) {                     // guard zeroing: slice b of 196608 halves
        const __half z = __float2half_rn(0.f);
        const int base = b * 12288;    // 196608 / 16
        for (int k = tid; k < 12288; k += 256) {
            int idx = base + k;
            if (idx < XGUARD * 512)
                g_Xh[idx] = z;
            else
                g_Xh[(size_t)(XGUARD + XROWS) * 512 + (idx - XGUARD * 512)] = z;
        }
        return;
    }

    const bool irow = (r >= 1 && r <= 32);
    for (int half = 0; half < 2; ++half) {
        const int cb = half * 256;
        __syncthreads();
        if (irow) {
            for (int idx = tid; idx < 256 * 32; idx += 256) {
                int ci = idx >> 5, cc = idx & 31;
                xt[ci][cc] = x[((size_t)(b * 512 + cb + ci) * 32 + (r - 1)) * 32 + cc]
                             * g_s[b * 512 + cb + ci];
            }
        }
        __syncthreads();
        for (int idx = tid; idx < 34 * 256; idx += 256) {
            int c = idx >> 8, ci = idx & 255;
            float v = (irow && c >= 1 && c <= 32) ? xt[ci][c - 1] : 0.f;
            size_t o = ((size_t)(b * 1156 + r * 34 + c) + XGUARD) * 512 + cb + ci;
            g_Xh[o] = __float2half_rn(v);
        }
    }
}

// ---------------------------------------------------------------------------
// Block tile: 128 co x 256 n x K-chunk 64. Warp tile 64x64 (8 warps, 2x4).
#define STAGES      3
#define TILE_A      0           // 128 x 64 fp16 = 16KB
#define TILE_B      16384       // 256 x 64 fp16 = 32KB
#define STAGE_BYTES 49152
#define NCHUNK      72          // 9 taps x 8 chunks of 64 ci

__device__ __forceinline__ void load_chunk(uint32_t su, int stage, int g,
                                           int co0, int n0, int tid) {
    const int tap = c_tap[g >> 3];
    const int kc  = (g & 7) << 6;
    const uint32_t sb = su + stage * STAGE_BYTES;
    // A: 128 rows x 8 c8 = 1024 cp16
#pragma unroll
    for (int t = 0; t < 4; ++t) {
        int idx = t * 256 + tid;
        int row = idx >> 3, c8 = idx & 7;
        size_t aoff = ((size_t)(tap * 512 + co0 + row)) * 512 + kc + c8 * 8;
        cp16(sb + TILE_A + swz(row, c8), g_Ah + aoff);
    }
    // B: 256 rows x 8 c8 = 2048 cp16 (shifted view into padded X)
    const long base = (long)n0 - c_shift[tap] + XGUARD;
#pragma unroll
    for (int t = 0; t < 8; ++t) {
        int idx = t * 256 + tid;
        int row = idx >> 3, c8 = idx & 7;
        size_t boff = (size_t)(base + row) * 512 + kc + c8 * 8;
        cp16(sb + TILE_B + swz(row, c8), g_Xh + boff);
    }
}

__device__ __forceinline__ void do_compute(uint32_t sb, float acc[4][8][4],
                                           int lane, int warp_m, int warp_n) {
#pragma unroll
    for (int ks = 0; ks < 4; ++ks) {
        uint32_t bh[16];
#pragma unroll
        for (int pr = 0; pr < 4; ++pr) {
            int brow = warp_n + pr * 16 + (lane & 7) + ((lane >> 4) & 1) * 8;
            int bc8  = ks * 2 + ((lane >> 3) & 1);
            ldsm_x4(&bh[pr * 4], sb + TILE_B + swz(brow, bc8));
        }
#pragma unroll
        for (int mt = 0; mt < 4; ++mt) {
            int arow = warp_m + mt * 16 + (lane & 15);
            int ac8  = ks * 2 + ((lane >> 4) & 1);
            uint32_t ah[4];
            ldsm_x4(ah, sb + TILE_A + swz(arow, ac8));
#pragma unroll
            for (int nt = 0; nt < 8; ++nt) {
                mma_fp16(acc[mt][nt], ah, &bh[(nt >> 1) * 4 + (nt & 1) * 2]);
            }
        }
    }
}

__device__ __forceinline__ void epilogue(float acc[4][8][4], int p, int co0,
                                         int n0, int lane, int warp_m, int warp_n) {
    const int rr = lane >> 2, q = lane & 3;
#pragma unroll
    for (int mt = 0; mt < 4; ++mt) {
        const int co = co0 + warp_m + mt * 16 + rr;
#pragma unroll
        for (int nt = 0; nt < 8; ++nt) {
            int n = n0 + warp_n + nt * 8 + q * 2;
            if (n < XROWS) {
                int b = n / 1156;
                int rem = n - b * 1156;   // even: half2 stays in-row and aligned
                __half2 v0 = __floats2half2_rn(acc[mt][nt][0], acc[mt][nt][1]);
                __half2 v1 = __floats2half2_rn(acc[mt][nt][2], acc[mt][nt][3]);
                *(__half2*)(g_y + (((size_t)(b * 512 + co) * 4 + p) * 1156 + rem)) = v0;
                *(__half2*)(g_y + (((size_t)(b * 512 + co + 8) * 4 + p) * 1156 + rem)) = v1;
            }
        }
    }
}

__global__ __launch_bounds__(256, 1) void k_gemm() {
    extern __shared__ char smem[];
    const uint32_t su = smem_to_u32(smem);
    const int tid = threadIdx.x;
    const int lane = tid & 31, wid = tid >> 5;
    const int warp_m = (wid >> 2) * 64;
    const int warp_n = (wid & 3) * 64;
    const int n0  = blockIdx.x * 256;
    const int co0 = blockIdx.y * 128;

    float acc[4][8][4];
#pragma unroll
    for (int a = 0; a < 4; ++a)
#pragma unroll
        for (int b = 0; b < 8; ++b)
#pragma unroll
            for (int c = 0; c < 4; ++c) acc[a][b][c] = 0.f;

#pragma unroll
    for (int s = 0; s < STAGES - 1; ++s) {
        load_chunk(su, s, s, co0, n0, tid);
        cp_commit();
    }

    for (int g = 0; g < NCHUNK; ++g) {
        cp_wait1();                       // oldest (chunk g) resident
        __syncthreads();                  // single barrier per chunk
        if (g + STAGES - 1 < NCHUNK)
            load_chunk(su, (g + STAGES - 1) % STAGES, g + STAGES - 1, co0, n0, tid);
        cp_commit();
        do_compute(su + (g % STAGES) * STAGE_BYTES, acc, lane, warp_m, warp_n);
        if (g == 31 || g == 47 || g == 63 || g == 71) {
            const int p = (g == 31) ? 0 : (g == 47) ? 1 : (g == 63) ? 2 : 3;
            epilogue(acc, p, co0, n0, lane, warp_m, warp_n);
#pragma unroll
            for (int a = 0; a < 4; ++a)
#pragma unroll
                for (int b = 0; b < 8; ++b)
#pragma unroll
                    for (int c = 0; c < 4; ++c) acc[a][b][c] = 0.f;
        }
    }
}

// ---------------------------------------------------------------------------
__global__ __launch_bounds__(256) void k_blur(float* __restrict__ z,
                                              const float* __restrict__ bias) {
    __shared__ float ys[67][68];
    const int co = blockIdx.x, b = blockIdx.y;
    const int tid = threadIdx.x;

    for (int idx = tid; idx < 67 * 68; idx += 256) ((float*)ys)[idx] = 0.f;
    __syncthreads();

    const __half* yb = g_y + ((size_t)(b * 512 + co)) * 4 * 1156;
    for (int idx = tid; idx < 4 * 33 * 33; idx += 256) {
        int p = idx / 1089, rem = idx - p * 1089;
        int i = rem / 33, j = rem - i * 33;
        float v = __half2float(yb[(size_t)p * 1156 + (i + 1) * 34 + (j + 1)]);
        ys[2 * i + (p >> 1) + 1][2 * j + (p & 1) + 1] = v;
    }
    __syncthreads();

    const float dd = g_d[b * COUT_ + co];
    const float bv = bias[co];
    const int u = tid >> 2;
    const int v0 = (tid & 3) * 16;

    float col[19];
#pragma unroll
    for (int m = 0; m < 19; ++m) {
        col[m] = ys[u][v0 + m] + 3.f * ys[u + 1][v0 + m]
               + 3.f * ys[u + 2][v0 + m] + ys[u + 3][v0 + m];
    }
    float* zp = z + (((size_t)b * COUT_ + co) * 64 + u) * 64 + v0;
#pragma unroll
    for (int m = 0; m < 16; ++m) {
        float h = col[m] + 3.f * col[m + 1] + 3.f * col[m + 2] + col[m + 3];
        zp[m] = dd * (h * (1.f / 16.f)) + bv;
    }
}

// ---------------------------------------------------------------------------
extern "C" void kernel_launch(void* const* d_in, const int* in_sizes, int n_in,
                              void* d_out, int out_size) {
    const float* x    = (const float*)d_in[0];
    const float* w    = (const float*)d_in[1];
    const float* wt   = (const float*)d_in[2];
    const float* bias = (const float*)d_in[3];
    const float* aw   = (const float*)d_in[4];
    const float* ab   = (const float*)d_in[5];
    float* z = (float*)d_out;

    cudaFuncSetAttribute(k_gemm, cudaFuncAttributeMaxDynamicSharedMemorySize,
                         STAGES * STAGE_BYTES);

    // k_gemm is our 4th launch: with the harness's ~2 internal launches,
    // ncu -s 5 -c 1 should finally land on it.
    k_style<<<B_, CIN_>>>(w, aw, ab);                       // 1
    k_prepx<<<dim3(35, B_), 256>>>(x);                      // 2 (guard merged)
    k_prepw<<<COUT_, 256>>>(wt);                            // 3
    k_gemm<<<dim3(NT2, 4), 256, STAGES * STAGE_BYTES>>>();  // 4  <- profile target
    k_demod<<<B_, COUT_>>>();                               // 5
    k_blur<<<dim3(COUT_, B_), 256>>>(z, bias);              // 6
}

// round 12
// speedup vs baseline: 1.6180x; 1.6180x over previous
#include <cuda_runtime.h>
#include <cuda_fp16.h>
#include <cstdint>

#define B_    16
#define CIN_  512
#define COUT_ 512
#define LAT_  512

#define XROWS  18496            // 16 * 34 * 34
#define XGUARD 64               // front zero rows
#define XTAIL  320              // tail zero rows (covers 256-row B tiles past end)
#define NT2    73               // ceil(18496/256)

// ---------------- device globals (allocation-free scratch) ------------------
__device__ float g_s[B_ * CIN_];
__device__ float g_wsq[COUT_ * CIN_];
__device__ float g_d[B_ * COUT_];
__device__ __half g_y[(size_t)B_ * COUT_ * 4 * 1156];    // [b][co][p][34][34] fp16

__device__ __align__(256) __half g_Ah[9ull * 512 * 512];   // [tap][co][ci]
__device__ __align__(256) __half g_Xh[(size_t)(XGUARD + XROWS + XTAIL) * 512];

// tap order grouped by parity: p0={0,2,6,8} p1={1,7} p2={3,5} p3={4}
__constant__ int c_tap[9]   = {0, 2, 6, 8, 1, 7, 3, 5, 4};
// shift[t] = (kh>>1)*34 + (kw>>1), indexed by tap id
__constant__ int c_shift[9] = {0, 0, 1, 0, 0, 1, 34, 34, 35};

// ---------------- helpers ---------------------------------------------------
__device__ __forceinline__ uint32_t smem_to_u32(const void* p) {
    uint32_t a;
    asm("{ .reg .u64 t; cvta.to.shared.u64 t, %1; cvt.u32.u64 %0, t; }"
        : "=r"(a) : "l"(p));
    return a;
}
__device__ __forceinline__ void cp16(uint32_t dst, const void* src) {
    asm volatile("cp.async.cg.shared.global [%0], [%1], 16;\n"
                 :: "r"(dst), "l"(src));
}
__device__ __forceinline__ void cp_commit() {
    asm volatile("cp.async.commit_group;\n" ::: "memory");
}
__device__ __forceinline__ void cp_wait2() {
    asm volatile("cp.async.wait_group 2;\n" ::: "memory");
}
__device__ __forceinline__ void ldsm_x4(uint32_t* r, uint32_t addr) {
    asm volatile("ldmatrix.sync.aligned.m8n8.x4.shared.b16 {%0,%1,%2,%3}, [%4];"
                 : "=r"(r[0]), "=r"(r[1]), "=r"(r[2]), "=r"(r[3]) : "r"(addr));
}
__device__ __forceinline__ void mma_fp16(float* d, const uint32_t* a,
                                         const uint32_t* b) {
    asm volatile(
        "mma.sync.aligned.m16n8k16.row.col.f32.f16.f16.f32 "
        "{%0,%1,%2,%3}, {%4,%5,%6,%7}, {%8,%9}, {%0,%1,%2,%3};"
        : "+f"(d[0]), "+f"(d[1]), "+f"(d[2]), "+f"(d[3])
        : "r"(a[0]), "r"(a[1]), "r"(a[2]), "r"(a[3]), "r"(b[0]), "r"(b[1]));
}
// smem tile rows of 64 fp16 (128B), xor-swizzled 16B chunks, 8-row period
__device__ __forceinline__ int swz(int row, int c8) {
    return row * 128 + ((c8 ^ (row & 7)) << 4);
}

// ---------------------------------------------------------------------------
__global__ void k_style(const float* __restrict__ w, const float* __restrict__ aw,
                        const float* __restrict__ ab) {
    int b = blockIdx.x, ci = threadIdx.x;
    const float* wr = w + b * LAT_;
    const float* ar = aw + (size_t)ci * LAT_;
    float acc = 0.f;
#pragma unroll 8
    for (int l = 0; l < LAT_; ++l) acc += wr[l] * ar[l];
    g_s[b * CIN_ + ci] = acc + ab[ci] + 1.0f;
}

__global__ void k_demod() {
    int b = blockIdx.x, co = threadIdx.x;
    __shared__ float s2[CIN_];
    for (int i = threadIdx.x; i < CIN_; i += blockDim.x) {
        float v = g_s[b * CIN_ + i];
        s2[i] = v * v;
    }
    __syncthreads();
    const float* wq = g_wsq + (size_t)co * CIN_;
    float a = 0.f;
#pragma unroll 8
    for (int ci = 0; ci < CIN_; ++ci) a += s2[ci] * wq[ci];
    g_d[b * COUT_ + co] = rsqrtf(a + 1e-8f);
}

// A prep + wsq (merged): g_Ah[tap][co][ci] = fp16(weight[co][ci][tap]),
// g_wsq[co][ci] = sum_t weight^2
__global__ __launch_bounds__(256) void k_prepw(const float* __restrict__ weight) {
    const int co = blockIdx.x;
#pragma unroll
    for (int r = 0; r < 2; ++r) {
        const int ci = threadIdx.x * 2 + r;
        const float* p = weight + ((size_t)co * 512 + ci) * 9;
        float sq = 0.f;
#pragma unroll
        for (int t = 0; t < 9; ++t) {
            float v = p[t];
            g_Ah[((size_t)t * 512 + co) * 512 + ci] = __float2half_rn(v);
            sq += v * v;
        }
        g_wsq[(size_t)co * 512 + ci] = sq;
    }
}

// Xp prep: row n = b*1156 + r*34 + c ; Xp = x*s interior, 0 on r,c in {0,33}
__global__ __launch_bounds__(256) void k_prepx(const float* __restrict__ x) {
    __shared__ float xt[256][33];
    const int r = blockIdx.x;          // 0..33
    const int b = blockIdx.y;
    const int tid = threadIdx.x;
    const bool irow = (r >= 1 && r <= 32);
    for (int half = 0; half < 2; ++half) {
        const int cb = half * 256;
        __syncthreads();
        if (irow) {
            for (int idx = tid; idx < 256 * 32; idx += 256) {
                int ci = idx >> 5, cc = idx & 31;
                xt[ci][cc] = x[((size_t)(b * 512 + cb + ci) * 32 + (r - 1)) * 32 + cc]
                             * g_s[b * 512 + cb + ci];
            }
        }
        __syncthreads();
        for (int idx = tid; idx < 34 * 256; idx += 256) {
            int c = idx >> 8, ci = idx & 255;
            float v = (irow && c >= 1 && c <= 32) ? xt[ci][c - 1] : 0.f;
            size_t o = ((size_t)(b * 1156 + r * 34 + c) + XGUARD) * 512 + cb + ci;
            g_Xh[o] = __float2half_rn(v);
        }
    }
}

__global__ void k_guard() {
    int idx = blockIdx.x * 256 + threadIdx.x;       // (64+320)*512 = 196608 total
    __half z = __float2half_rn(0.f);
    if (idx < XGUARD * 512) {
        g_Xh[idx] = z;
    } else {
        g_Xh[(size_t)(XGUARD + XROWS) * 512 + (idx - XGUARD * 512)] = z;
    }
}

// ---------------------------------------------------------------------------
// Block tile: 128 co x 256 n x K-chunk 64. Warp tile 64x64 (8 warps, 2x4).
// STAGES=4 (192KB smem): extra cp.async slack to cover L2 latency at tap
// boundaries where B's base address jumps.
#define STAGES      4
#define TILE_A      0           // 128 x 64 fp16 = 16KB
#define TILE_B      16384       // 256 x 64 fp16 = 32KB
#define STAGE_BYTES 49152
#define NCHUNK      72          // 9 taps x 8 chunks of 64 ci

__device__ __forceinline__ void load_chunk(uint32_t su, int stage, int g,
                                           int co0, int n0, int tid) {
    const int tap = c_tap[g >> 3];
    const int kc  = (g & 7) << 6;
    const uint32_t sb = su + stage * STAGE_BYTES;
    // A: 128 rows x 8 c8 = 1024 cp16
#pragma unroll
    for (int t = 0; t < 4; ++t) {
        int idx = t * 256 + tid;
        int row = idx >> 3, c8 = idx & 7;
        size_t aoff = ((size_t)(tap * 512 + co0 + row)) * 512 + kc + c8 * 8;
        cp16(sb + TILE_A + swz(row, c8), g_Ah + aoff);
    }
    // B: 256 rows x 8 c8 = 2048 cp16 (shifted view into padded X)
    const long base = (long)n0 - c_shift[tap] + XGUARD;
#pragma unroll
    for (int t = 0; t < 8; ++t) {
        int idx = t * 256 + tid;
        int row = idx >> 3, c8 = idx & 7;
        size_t boff = (size_t)(base + row) * 512 + kc + c8 * 8;
        cp16(sb + TILE_B + swz(row, c8), g_Xh + boff);
    }
}

__device__ __forceinline__ void do_compute(uint32_t sb, float acc[4][8][4],
                                           int lane, int warp_m, int warp_n) {
#pragma unroll
    for (int ks = 0; ks < 4; ++ks) {
        uint32_t bh[16];
#pragma unroll
        for (int pr = 0; pr < 4; ++pr) {
            int brow = warp_n + pr * 16 + (lane & 7) + ((lane >> 4) & 1) * 8;
            int bc8  = ks * 2 + ((lane >> 3) & 1);
            ldsm_x4(&bh[pr * 4], sb + TILE_B + swz(brow, bc8));
        }
#pragma unroll
        for (int mt = 0; mt < 4; ++mt) {
            int arow = warp_m + mt * 16 + (lane & 15);
            int ac8  = ks * 2 + ((lane >> 4) & 1);
            uint32_t ah[4];
            ldsm_x4(ah, sb + TILE_A + swz(arow, ac8));
#pragma unroll
            for (int nt = 0; nt < 8; ++nt) {
                mma_fp16(acc[mt][nt], ah, &bh[(nt >> 1) * 4 + (nt & 1) * 2]);
            }
        }
    }
}

__device__ __forceinline__ void epilogue(float acc[4][8][4], int p, int co0,
                                         int n0, int lane, int warp_m, int warp_n) {
    const int rr = lane >> 2, q = lane & 3;
#pragma unroll
    for (int mt = 0; mt < 4; ++mt) {
        const int co = co0 + warp_m + mt * 16 + rr;
#pragma unroll
        for (int nt = 0; nt < 8; ++nt) {
            int n = n0 + warp_n + nt * 8 + q * 2;
            if (n < XROWS) {
                int b = n / 1156;
                int rem = n - b * 1156;   // even: half2 stays in-row and aligned
                __half2 v0 = __floats2half2_rn(acc[mt][nt][0], acc[mt][nt][1]);
                __half2 v1 = __floats2half2_rn(acc[mt][nt][2], acc[mt][nt][3]);
                *(__half2*)(g_y + (((size_t)(b * 512 + co) * 4 + p) * 1156 + rem)) = v0;
                *(__half2*)(g_y + (((size_t)(b * 512 + co + 8) * 4 + p) * 1156 + rem)) = v1;
            }
        }
    }
}

__global__ __launch_bounds__(256, 1) void k_gemm() {
    extern __shared__ char smem[];
    const uint32_t su = smem_to_u32(smem);
    const int tid = threadIdx.x;
    const int lane = tid & 31, wid = tid >> 5;
    const int warp_m = (wid >> 2) * 64;
    const int warp_n = (wid & 3) * 64;
    const int n0  = blockIdx.x * 256;
    const int co0 = blockIdx.y * 128;

    float acc[4][8][4];
#pragma unroll
    for (int a = 0; a < 4; ++a)
#pragma unroll
        for (int b = 0; b < 8; ++b)
#pragma unroll
            for (int c = 0; c < 4; ++c) acc[a][b][c] = 0.f;

#pragma unroll
    for (int s = 0; s < STAGES - 1; ++s) {
        load_chunk(su, s, s, co0, n0, tid);
        cp_commit();
    }

    for (int g = 0; g < NCHUNK; ++g) {
        cp_wait2();                       // oldest (chunk g) resident, 2 pending
        __syncthreads();                  // single barrier per chunk
        if (g + STAGES - 1 < NCHUNK)
            load_chunk(su, (g + STAGES - 1) % STAGES, g + STAGES - 1, co0, n0, tid);
        cp_commit();
        do_compute(su + (g % STAGES) * STAGE_BYTES, acc, lane, warp_m, warp_n);
        if (g == 31 || g == 47 || g == 63 || g == 71) {
            const int p = (g == 31) ? 0 : (g == 47) ? 1 : (g == 63) ? 2 : 3;
            epilogue(acc, p, co0, n0, lane, warp_m, warp_n);
#pragma unroll
            for (int a = 0; a < 4; ++a)
#pragma unroll
                for (int b = 0; b < 8; ++b)
#pragma unroll
                    for (int c = 0; c < 4; ++c) acc[a][b][c] = 0.f;
        }
    }
}

// ---------------------------------------------------------------------------
__global__ __launch_bounds__(256) void k_blur(float* __restrict__ z,
                                              const float* __restrict__ bias) {
    __shared__ float ys[67][68];
    const int co = blockIdx.x, b = blockIdx.y;
    const int tid = threadIdx.x;

    for (int idx = tid; idx < 67 * 68; idx += 256) ((float*)ys)[idx] = 0.f;
    __syncthreads();

    const __half* yb = g_y + ((size_t)(b * 512 + co)) * 4 * 1156;
    for (int idx = tid; idx < 4 * 33 * 33; idx += 256) {
        int p = idx / 1089, rem = idx - p * 1089;
        int i = rem / 33, j = rem - i * 33;
        float v = __half2float(yb[(size_t)p * 1156 + (i + 1) * 34 + (j + 1)]);
        ys[2 * i + (p >> 1) + 1][2 * j + (p & 1) + 1] = v;
    }
    __syncthreads();

    const float dd = g_d[b * COUT_ + co];
    const float bv = bias[co];
    const int u = tid >> 2;
    const int v0 = (tid & 3) * 16;

    float col[19];
#pragma unroll
    for (int m = 0; m < 19; ++m) {
        col[m] = ys[u][v0 + m] + 3.f * ys[u + 1][v0 + m]
               + 3.f * ys[u + 2][v0 + m] + ys[u + 3][v0 + m];
    }
    float* zp = z + (((size_t)b * COUT_ + co) * 64 + u) * 64 + v0;
#pragma unroll
    for (int m = 0; m < 16; ++m) {
        float h = col[m] + 3.f * col[m + 1] + 3.f * col[m + 2] + col[m + 3];
        zp[m] = dd * (h * (1.f / 16.f)) + bv;
    }
}

// ---------------------------------------------------------------------------
extern "C" void kernel_launch(void* const* d_in, const int* in_sizes, int n_in,
                              void* d_out, int out_size) {
    const float* x    = (const float*)d_in[0];
    const float* w    = (const float*)d_in[1];
    const float* wt   = (const float*)d_in[2];
    const float* bias = (const float*)d_in[3];
    const float* aw   = (const float*)d_in[4];
    const float* ab   = (const float*)d_in[5];
    float* z = (float*)d_out;

    cudaFuncSetAttribute(k_gemm, cudaFuncAttributeMaxDynamicSharedMemorySize,
                         STAGES * STAGE_BYTES);

    // Exact R8 launch structure (known-good 709us baseline); only STAGES changed.
    k_style<<<B_, CIN_>>>(w, aw, ab);
    k_prepx<<<dim3(34, B_), 256>>>(x);
    k_guard<<<768, 256>>>();
    k_prepw<<<COUT_, 256>>>(wt);
    k_demod<<<B_, COUT_>>>();
    k_gemm<<<dim3(NT2, 4), 256, STAGES * STAGE_BYTES>>>();
    k_blur<<<dim3(COUT_, B_), 256>>>(z, bias);
}